// round 13
// baseline (speedup 1.0000x reference)
#include <cuda_runtime.h>
#include <cuda_fp16.h>
#include <math.h>
#include <float.h>
#include <stdint.h>

#define EPS 1e-8f
#define LR  0.1f
#define THRESH 5e-3f

#define MAXB 131072
#define MAXS 1024
#define DD   256

// Global scratch
__device__ float  g_kn[(size_t)MAXS * DD];    // normalized keys fp32 (rescore)
__device__ __half g_kh[(size_t)MAXS * DD];    // normalized keys fp16 (GEMM)
__device__ int    g_idx[MAXB];
__device__ int    g_winner[MAXS];
__device__ int    g_flagged[MAXB];
__device__ int    g_nflag;

// ---------------------------------------------------------------------------
__device__ __forceinline__ uint32_t smem_u32(const void* p) {
    uint32_t a;
    asm("{ .reg .u64 t; cvta.to.shared.u64 t, %1; cvt.u32.u64 %0, t; }" : "=r"(a) : "l"(p));
    return a;
}
__device__ __forceinline__ void cpasync16(uint32_t saddr, const void* gaddr) {
    asm volatile("cp.async.cg.shared.global [%0], [%1], 16;" :: "r"(saddr), "l"(gaddr));
}
#define CP_COMMIT()  asm volatile("cp.async.commit_group;" ::: "memory")
#define CP_WAIT(n)   asm volatile("cp.async.wait_group %0;" :: "n"(n) : "memory")

__device__ __forceinline__ void ldm4(uint32_t* d, uint32_t addr) {
    asm volatile("ldmatrix.sync.aligned.m8n8.x4.shared.b16 {%0,%1,%2,%3}, [%4];"
        : "=r"(d[0]), "=r"(d[1]), "=r"(d[2]), "=r"(d[3]) : "r"(addr));
}
__device__ __forceinline__ void mma16816(float* c, const uint32_t* a, const uint32_t* b) {
    asm volatile(
        "mma.sync.aligned.m16n8k16.row.col.f32.f16.f16.f32 "
        "{%0,%1,%2,%3}, {%4,%5,%6,%7}, {%8,%9}, {%0,%1,%2,%3};"
        : "+f"(c[0]), "+f"(c[1]), "+f"(c[2]), "+f"(c[3])
        : "r"(a[0]), "r"(a[1]), "r"(a[2]), "r"(a[3]), "r"(b[0]), "r"(b[1]));
}
__device__ __forceinline__ float4 ldcs4(const float4* p) {
    float4 v;
    asm volatile("ld.global.cs.v4.f32 {%0,%1,%2,%3}, [%4];"
        : "=f"(v.x), "=f"(v.y), "=f"(v.z), "=f"(v.w) : "l"(p));
    return v;
}
__device__ __forceinline__ void stcs4(float4* p, float4 v) {
    asm volatile("st.global.cs.v4.f32 [%0], {%1,%2,%3,%4};"
        :: "l"(p), "f"(v.x), "f"(v.y), "f"(v.z), "f"(v.w) : "memory");
}

// ---------------------------------------------------------------------------
// Prep: normalize keys -> fp32 + fp16; init winner=-1, nflag=0
// ---------------------------------------------------------------------------
__global__ void knorm_kernel(const float* __restrict__ keys, int S, int D) {
    int s = blockIdx.x;
    int t = threadIdx.x;
    __shared__ float red[8];
    __shared__ float s_nrm;
    float v = keys[(size_t)s * D + t];
    float sq = v * v;
    #pragma unroll
    for (int o = 16; o; o >>= 1) sq += __shfl_xor_sync(0xFFFFFFFFu, sq, o);
    if ((t & 31) == 0) red[t >> 5] = sq;
    __syncthreads();
    if (t == 0) {
        float tot = 0.0f;
        #pragma unroll
        for (int i = 0; i < 8; i++) tot += red[i];
        s_nrm = fmaxf(sqrtf(tot), EPS);
        g_winner[s] = -1;
        if (s == 0) g_nflag = 0;
    }
    __syncthreads();
    float kn = v / s_nrm;
    g_kn[(size_t)s * D + t] = kn;
    g_kh[(size_t)s * D + t] = __float2half_rn(kn);
}

// ---------------------------------------------------------------------------
// Stage 1: fp16 m16n8k16 (f32 acc) GEMM + argmax + gap filter + fused gather.
// CTA: 128 query rows, 256 threads, 8 warps = 4 wM x 2 wN, 2 CTAs/SM.
// (identical to R11 — measured ~93% of rt8 HMMA floor)
// ---------------------------------------------------------------------------
#define ASTB 528                      // A row stride bytes
#define BSTB 144                      // B row stride bytes
#define SM_A   0
#define SM_B   (128 * ASTB)           // 67584
#define BBUF   (128 * BSTB)           // 18432
#define SM_TOTAL (SM_B + 2 * BBUF)    // 104448
#define RED_V  (SM_B)
#define RED_I  (SM_B + 128*2*4)
#define RED_V2 (SM_B + 128*2*4*2)
#define RED_FI (SM_B + 128*2*4*3)

__global__ void __launch_bounds__(256, 2)
score_argmax_kernel(const float* __restrict__ q,
                    const float* __restrict__ vals,
                    float* __restrict__ out_read, int B, int S) {
    extern __shared__ char sm[];
    const uint32_t smb = smem_u32(sm);
    const int tid  = threadIdx.x;
    const int wid  = tid >> 5;
    const int lane = tid & 31;
    const int wM   = wid >> 1;        // 0..3
    const int wN   = wid & 1;         // 0..1
    const int qrow = lane >> 2;       // 0..7
    const int qk   = lane & 3;        // 0..3
    const int bm0  = blockIdx.x * 128;

    const int n_chunks = (S / 128) * 4;   // 32
    auto issueB = [&](int c) {
        int nt = c >> 2, kc = c & 3, buf = c & 1;
        #pragma unroll
        for (int i = 0; i < 4; i++) {
            int s2  = tid + i * 256;
            int row = s2 >> 3, seg = s2 & 7;
            const __half* g = g_kh + (size_t)(nt * 128 + row) * DD + kc * 64 + seg * 8;
            cpasync16(smb + SM_B + buf * BBUF + (uint32_t)(row * BSTB + seg * 16), g);
        }
        CP_COMMIT();
    };

    issueB(0);

    // ---- A: load q fp32 (evict-first), convert fp16, store padded ----
    {
        const float* qb = q + (size_t)bm0 * DD;
        #pragma unroll
        for (int i = tid; i < 128 * 64; i += 256) {
            int r  = i >> 6;
            int c4 = (i & 63) * 4;
            float4 v = ldcs4((const float4*)(qb + (size_t)r * DD + c4));
            __half2 h0 = __floats2half2_rn(v.x, v.y);
            __half2 h1 = __floats2half2_rn(v.z, v.w);
            uint2 pk = { *(uint32_t*)&h0, *(uint32_t*)&h1 };
            *(uint2*)(sm + SM_A + r * ASTB + c4 * 2) = pk;
        }
    }

    const uint32_t aBase = smb + SM_A +
        (uint32_t)((wM * 32 + ((lane >> 3) & 1) * 8 + (lane & 7)) * ASTB + (lane >> 4) * 16);
    const uint32_t bBase0 = smb + SM_B +
        (uint32_t)((wN * 64 + ((lane >> 4) & 1) * 8 + (lane & 7)) * BSTB + ((lane >> 3) & 1) * 16);

    float bv[4], bv2[4];
    int   bi[4];
    #pragma unroll
    for (int r = 0; r < 4; r++) { bv[r] = -FLT_MAX; bv2[r] = -FLT_MAX; bi[r] = 0; }

    for (int nt = 0; nt < S / 128; nt++) {
        float acc[2][8][4];
        #pragma unroll
        for (int mt = 0; mt < 2; mt++)
            #pragma unroll
            for (int j = 0; j < 8; j++)
                #pragma unroll
                for (int e = 0; e < 4; e++) acc[mt][j][e] = 0.0f;

        #pragma unroll
        for (int kc = 0; kc < 4; kc++) {
            const int c = nt * 4 + kc;
            const int buf = c & 1;
            CP_WAIT(0);
            __syncthreads();               // chunk-c data visible AND compute(c-1) done
            if (c + 1 < n_chunks) issueB(c + 1);

            const uint32_t bBase = bBase0 + (uint32_t)buf * BBUF;

            #pragma unroll
            for (int ks = 0; ks < 4; ks++) {
                uint32_t a0[4], a1[4];
                ldm4(a0, aBase + (uint32_t)(kc * 128 + ks * 32));
                ldm4(a1, aBase + (uint32_t)(16 * ASTB + kc * 128 + ks * 32));
                #pragma unroll
                for (int jp = 0; jp < 4; jp++) {
                    uint32_t bb[4];
                    ldm4(bb, bBase + (uint32_t)(jp * (16 * BSTB) + ks * 32));
                    mma16816(acc[0][jp * 2 + 0], a0, bb);
                    mma16816(acc[0][jp * 2 + 1], a0, bb + 2);
                    mma16816(acc[1][jp * 2 + 0], a1, bb);
                    mma16816(acc[1][jp * 2 + 1], a1, bb + 2);
                }
            }
        }

        // running argmax + 2nd max over this 128-key tile
        #pragma unroll
        for (int j = 0; j < 8; j++) {
            int col0 = nt * 128 + wN * 64 + j * 8 + 2 * qk;
            #pragma unroll
            for (int mt = 0; mt < 2; mt++)
                #pragma unroll
                for (int rr = 0; rr < 2; rr++) {
                    int r = mt * 2 + rr;
                    float v0 = acc[mt][j][rr * 2 + 0];
                    float v1 = acc[mt][j][rr * 2 + 1];
                    if (v0 > bv[r]) { bv2[r] = bv[r]; bv[r] = v0; bi[r] = col0; }
                    else            { bv2[r] = fmaxf(bv2[r], v0); }
                    if (v1 > bv[r]) { bv2[r] = bv[r]; bv[r] = v1; bi[r] = col0 + 1; }
                    else            { bv2[r] = fmaxf(bv2[r], v1); }
                }
        }
    }
    __syncthreads();   // all compute done before reduce scratch reuses B area

    // ---- quad reduce ----
    #pragma unroll
    for (int off = 1; off <= 2; off <<= 1) {
        #pragma unroll
        for (int r = 0; r < 4; r++) {
            float ov  = __shfl_xor_sync(0xFFFFFFFFu, bv[r],  off);
            int   oi  = __shfl_xor_sync(0xFFFFFFFFu, bi[r],  off);
            float ov2 = __shfl_xor_sync(0xFFFFFFFFu, bv2[r], off);
            if (ov > bv[r]) { bv2[r] = fmaxf(bv[r], ov2); bv[r] = ov; bi[r] = oi; }
            else {
                if (ov == bv[r] && oi < bi[r]) bi[r] = oi;
                bv2[r] = fmaxf(bv2[r], ov);
            }
        }
    }

    // ---- cross-warp (wN) reduce ----
    float* rv  = (float*)(sm + RED_V);
    int*   ri  = (int*)  (sm + RED_I);
    float* rv2 = (float*)(sm + RED_V2);
    int*   rfi = (int*)  (sm + RED_FI);
    if (qk == 0) {
        #pragma unroll
        for (int r = 0; r < 4; r++) {
            int mt = r >> 1, rr = r & 1;
            int row = wM * 32 + mt * 16 + rr * 8 + qrow;
            rv [row * 2 + wN] = bv[r];
            ri [row * 2 + wN] = bi[r];
            rv2[row * 2 + wN] = bv2[r];
        }
    }
    __syncthreads();
    if (tid < 128) {
        float fv = rv[tid * 2], fv2 = rv2[tid * 2];
        int   fi = ri[tid * 2];
        float ov = rv[tid * 2 + 1], ov2 = rv2[tid * 2 + 1];
        int   oi = ri[tid * 2 + 1];
        if (ov > fv) { fv2 = fmaxf(fv, ov2); fv = ov; fi = oi; }
        else {
            if (ov == fv && oi < fi) fi = oi;
            fv2 = fmaxf(fv2, ov);
        }
        int b = bm0 + tid;
        g_idx[b] = fi;
        rfi[tid] = fi;
        if (fv - fv2 < THRESH) {
            int p = atomicAdd(&g_nflag, 1);
            g_flagged[p] = b;          // rescore votes + rewrites out row
        } else {
            atomicMax(&g_winner[fi], b);
        }
    }
    __syncthreads();

    // ---- fused gather: out_read[bm0+row] = vals[rfi[row]] ----
    {
        const float4* v4 = (const float4*)vals;
        float4* o4 = (float4*)(out_read + (size_t)bm0 * DD);
        #pragma unroll
        for (int i = tid; i < 128 * 64; i += 256) {
            int row = i >> 6, c4 = i & 63;
            stcs4(&o4[(size_t)row * 64 + c4], v4[(size_t)rfi[row] * 64 + c4]);
        }
    }
}

// ---------------------------------------------------------------------------
// Stage 2: exact fp32 rescore — ONE flagged row per block (high parallelism).
// 256 threads: thread t handles keys t, 256+t, 512+t, 768+t (ascending).
// Per-(row,key) accumulation order identical to the previous rescore
// (d4 ascending, x,y,z,w) => bit-identical scores and tie semantics.
// ---------------------------------------------------------------------------
__global__ void __launch_bounds__(256)
rescore_kernel(const float* __restrict__ q, const float* __restrict__ vals,
               float* __restrict__ out_read, int S) {
    __shared__ float sq[256];
    __shared__ float rv[8];
    __shared__ int   rix[8];
    __shared__ int   s_fi;
    const int tid  = threadIdx.x;
    const int wid  = tid >> 5;
    const int lane = tid & 31;
    const int nf = g_nflag;

    for (int fr = blockIdx.x; fr < nf; fr += gridDim.x) {
        const int b = g_flagged[fr];
        sq[tid] = q[(size_t)b * DD + tid];
        __syncthreads();

        float bvl = -FLT_MAX;
        int   bil = 0;
        #pragma unroll
        for (int kq = 0; kq < 4; kq++) {
            const int s = kq * 256 + tid;
            const float4* kr = (const float4*)(g_kn + (size_t)s * DD);
            float acc = 0.0f;
            #pragma unroll 8
            for (int d4 = 0; d4 < 64; d4++) {
                float4 kv = kr[d4];
                const float4 qv = *(const float4*)&sq[d4 * 4];
                acc = fmaf(qv.x, kv.x, acc);
                acc = fmaf(qv.y, kv.y, acc);
                acc = fmaf(qv.z, kv.z, acc);
                acc = fmaf(qv.w, kv.w, acc);
            }
            if (acc > bvl) { bvl = acc; bil = s; }   // keys ascending per thread
        }

        // warp reduce (tie -> lower idx)
        #pragma unroll
        for (int off = 16; off; off >>= 1) {
            float ov = __shfl_xor_sync(0xFFFFFFFFu, bvl, off);
            int   oi = __shfl_xor_sync(0xFFFFFFFFu, bil, off);
            if (ov > bvl || (ov == bvl && oi < bil)) { bvl = ov; bil = oi; }
        }
        if (lane == 0) { rv[wid] = bvl; rix[wid] = bil; }
        __syncthreads();
        if (tid == 0) {
            float fv = -FLT_MAX; int fi = S;
            #pragma unroll
            for (int w = 0; w < 8; w++) {
                float v = rv[w]; int i = rix[w];
                if (v > fv || (v == fv && i < fi)) { fv = v; fi = i; }
            }
            g_idx[b] = fi;
            s_fi = fi;
            atomicMax(&g_winner[fi], b);
        }
        __syncthreads();
        // rewrite out_read row for this flagged query
        out_read[(size_t)b * DD + tid] = vals[(size_t)s_fi * DD + tid];
        __syncthreads();   // sq/s_fi reuse safety for next grid-stride row
    }
}

// ---------------------------------------------------------------------------
// Gated scatter update
// ---------------------------------------------------------------------------
__global__ void update_kernel(const float* __restrict__ q,
                              const float* __restrict__ tgt,
                              const float* __restrict__ sur,
                              const float* __restrict__ keys,
                              const float* __restrict__ vals,
                              float* __restrict__ outK,
                              float* __restrict__ outV, int D) {
    int s = blockIdx.x;
    int d = threadIdx.x;
    int b = g_winner[s];
    float k = keys[(size_t)s * D + d];
    float v = vals[(size_t)s * D + d];
    if (b >= 0) {
        float g  = (1.0f / (1.0f + expf(-4.0f * sur[b]))) * LR;
        float om = 1.0f - g;
        outK[(size_t)s * D + d] = om * k + g * q[(size_t)b * D + d];
        outV[(size_t)s * D + d] = om * v + g * tgt[(size_t)b * D + d];
    } else {
        outK[(size_t)s * D + d] = k;
        outV[(size_t)s * D + d] = v;
    }
}

// ---------------------------------------------------------------------------
extern "C" void kernel_launch(void* const* d_in, const int* in_sizes, int n_in,
                              void* d_out, int out_size) {
    const float* query    = (const float*)d_in[0];
    const float* target   = (const float*)d_in[1];
    const float* surprise = (const float*)d_in[2];
    const float* keys     = (const float*)d_in[3];
    const float* vals     = (const float*)d_in[4];

    const int B = in_sizes[2];
    const int D = in_sizes[0] / B;     // 256
    const int S = in_sizes[3] / D;     // 1024

    float* out      = (float*)d_out;
    float* out_read = out;
    float* out_keys = out + (size_t)B * D;
    float* out_vals = out + (size_t)(B + S) * D;

    knorm_kernel<<<S, 256>>>(keys, S, D);

    cudaFuncSetAttribute(score_argmax_kernel,
                         cudaFuncAttributeMaxDynamicSharedMemorySize, SM_TOTAL);
    score_argmax_kernel<<<B / 128, 256, SM_TOTAL>>>(query, vals, out_read, B, S);

    rescore_kernel<<<2048, 256>>>(query, vals, out_read, S);

    update_kernel<<<S, 256>>>(query, target, surprise, keys, vals,
                              out_keys, out_vals, D);
}

// round 14
// speedup vs baseline: 1.9116x; 1.9116x over previous
#include <cuda_runtime.h>
#include <cuda_fp16.h>
#include <math.h>
#include <float.h>
#include <stdint.h>

#define EPS 1e-8f
#define LR  0.1f
#define THRESH 5e-3f

#define MAXB 131072
#define MAXS 1024
#define DD   256

// Global scratch
__device__ float  g_kn[(size_t)MAXS * DD];    // normalized keys fp32 (rescore)
__device__ __half g_kh[(size_t)MAXS * DD];    // normalized keys fp16 (GEMM)
__device__ int    g_idx[MAXB];
__device__ int    g_winner[MAXS];
__device__ int    g_flagged[MAXB];
__device__ int    g_nflag;

// ---------------------------------------------------------------------------
__device__ __forceinline__ uint32_t smem_u32(const void* p) {
    uint32_t a;
    asm("{ .reg .u64 t; cvta.to.shared.u64 t, %1; cvt.u32.u64 %0, t; }" : "=r"(a) : "l"(p));
    return a;
}
__device__ __forceinline__ void cpasync16(uint32_t saddr, const void* gaddr) {
    asm volatile("cp.async.cg.shared.global [%0], [%1], 16;" :: "r"(saddr), "l"(gaddr));
}
#define CP_COMMIT()  asm volatile("cp.async.commit_group;" ::: "memory")
#define CP_WAIT(n)   asm volatile("cp.async.wait_group %0;" :: "n"(n) : "memory")

__device__ __forceinline__ void ldm4(uint32_t* d, uint32_t addr) {
    asm volatile("ldmatrix.sync.aligned.m8n8.x4.shared.b16 {%0,%1,%2,%3}, [%4];"
        : "=r"(d[0]), "=r"(d[1]), "=r"(d[2]), "=r"(d[3]) : "r"(addr));
}
__device__ __forceinline__ void mma16816(float* c, const uint32_t* a, const uint32_t* b) {
    asm volatile(
        "mma.sync.aligned.m16n8k16.row.col.f32.f16.f16.f32 "
        "{%0,%1,%2,%3}, {%4,%5,%6,%7}, {%8,%9}, {%0,%1,%2,%3};"
        : "+f"(c[0]), "+f"(c[1]), "+f"(c[2]), "+f"(c[3])
        : "r"(a[0]), "r"(a[1]), "r"(a[2]), "r"(a[3]), "r"(b[0]), "r"(b[1]));
}
__device__ __forceinline__ float4 ldcs4(const float4* p) {
    float4 v;
    asm volatile("ld.global.cs.v4.f32 {%0,%1,%2,%3}, [%4];"
        : "=f"(v.x), "=f"(v.y), "=f"(v.z), "=f"(v.w) : "l"(p));
    return v;
}
__device__ __forceinline__ void stcs4(float4* p, float4 v) {
    asm volatile("st.global.cs.v4.f32 [%0], {%1,%2,%3,%4};"
        :: "l"(p), "f"(v.x), "f"(v.y), "f"(v.z), "f"(v.w) : "memory");
}

// ---------------------------------------------------------------------------
// Prep: normalize keys -> fp32 + fp16; init winner=-1, nflag=0
// ---------------------------------------------------------------------------
__global__ void knorm_kernel(const float* __restrict__ keys, int S, int D) {
    int s = blockIdx.x;
    int t = threadIdx.x;
    __shared__ float red[8];
    __shared__ float s_nrm;
    float v = keys[(size_t)s * D + t];
    float sq = v * v;
    #pragma unroll
    for (int o = 16; o; o >>= 1) sq += __shfl_xor_sync(0xFFFFFFFFu, sq, o);
    if ((t & 31) == 0) red[t >> 5] = sq;
    __syncthreads();
    if (t == 0) {
        float tot = 0.0f;
        #pragma unroll
        for (int i = 0; i < 8; i++) tot += red[i];
        s_nrm = fmaxf(sqrtf(tot), EPS);
        g_winner[s] = -1;
        if (s == 0) g_nflag = 0;
    }
    __syncthreads();
    float kn = v / s_nrm;
    g_kn[(size_t)s * D + t] = kn;
    g_kh[(size_t)s * D + t] = __float2half_rn(kn);
}

// ---------------------------------------------------------------------------
// Stage 1: fp16 m16n8k16 (f32 acc) GEMM + argmax + gap filter + fused gather.
// CTA: 128 query rows, 256 threads, 8 warps = 4 wM x 2 wN, 2 CTAs/SM.
// (identical to R11 — measured ~93% of rt8 HMMA floor)
// ---------------------------------------------------------------------------
#define ASTB 528                      // A row stride bytes
#define BSTB 144                      // B row stride bytes
#define SM_A   0
#define SM_B   (128 * ASTB)           // 67584
#define BBUF   (128 * BSTB)           // 18432
#define SM_TOTAL (SM_B + 2 * BBUF)    // 104448
#define RED_V  (SM_B)
#define RED_I  (SM_B + 128*2*4)
#define RED_V2 (SM_B + 128*2*4*2)
#define RED_FI (SM_B + 128*2*4*3)

__global__ void __launch_bounds__(256, 2)
score_argmax_kernel(const float* __restrict__ q,
                    const float* __restrict__ vals,
                    float* __restrict__ out_read, int B, int S) {
    extern __shared__ char sm[];
    const uint32_t smb = smem_u32(sm);
    const int tid  = threadIdx.x;
    const int wid  = tid >> 5;
    const int lane = tid & 31;
    const int wM   = wid >> 1;        // 0..3
    const int wN   = wid & 1;         // 0..1
    const int qrow = lane >> 2;       // 0..7
    const int qk   = lane & 3;        // 0..3
    const int bm0  = blockIdx.x * 128;

    const int n_chunks = (S / 128) * 4;   // 32
    auto issueB = [&](int c) {
        int nt = c >> 2, kc = c & 3, buf = c & 1;
        #pragma unroll
        for (int i = 0; i < 4; i++) {
            int s2  = tid + i * 256;
            int row = s2 >> 3, seg = s2 & 7;
            const __half* g = g_kh + (size_t)(nt * 128 + row) * DD + kc * 64 + seg * 8;
            cpasync16(smb + SM_B + buf * BBUF + (uint32_t)(row * BSTB + seg * 16), g);
        }
        CP_COMMIT();
    };

    issueB(0);

    // ---- A: load q fp32 (evict-first), convert fp16, store padded ----
    {
        const float* qb = q + (size_t)bm0 * DD;
        #pragma unroll
        for (int i = tid; i < 128 * 64; i += 256) {
            int r  = i >> 6;
            int c4 = (i & 63) * 4;
            float4 v = ldcs4((const float4*)(qb + (size_t)r * DD + c4));
            __half2 h0 = __floats2half2_rn(v.x, v.y);
            __half2 h1 = __floats2half2_rn(v.z, v.w);
            uint2 pk = { *(uint32_t*)&h0, *(uint32_t*)&h1 };
            *(uint2*)(sm + SM_A + r * ASTB + c4 * 2) = pk;
        }
    }

    const uint32_t aBase = smb + SM_A +
        (uint32_t)((wM * 32 + ((lane >> 3) & 1) * 8 + (lane & 7)) * ASTB + (lane >> 4) * 16);
    const uint32_t bBase0 = smb + SM_B +
        (uint32_t)((wN * 64 + ((lane >> 4) & 1) * 8 + (lane & 7)) * BSTB + ((lane >> 3) & 1) * 16);

    float bv[4], bv2[4];
    int   bi[4];
    #pragma unroll
    for (int r = 0; r < 4; r++) { bv[r] = -FLT_MAX; bv2[r] = -FLT_MAX; bi[r] = 0; }

    for (int nt = 0; nt < S / 128; nt++) {
        float acc[2][8][4];
        #pragma unroll
        for (int mt = 0; mt < 2; mt++)
            #pragma unroll
            for (int j = 0; j < 8; j++)
                #pragma unroll
                for (int e = 0; e < 4; e++) acc[mt][j][e] = 0.0f;

        #pragma unroll
        for (int kc = 0; kc < 4; kc++) {
            const int c = nt * 4 + kc;
            const int buf = c & 1;
            CP_WAIT(0);
            __syncthreads();               // chunk-c data visible AND compute(c-1) done
            if (c + 1 < n_chunks) issueB(c + 1);

            const uint32_t bBase = bBase0 + (uint32_t)buf * BBUF;

            #pragma unroll
            for (int ks = 0; ks < 4; ks++) {
                uint32_t a0[4], a1[4];
                ldm4(a0, aBase + (uint32_t)(kc * 128 + ks * 32));
                ldm4(a1, aBase + (uint32_t)(16 * ASTB + kc * 128 + ks * 32));
                #pragma unroll
                for (int jp = 0; jp < 4; jp++) {
                    uint32_t bb[4];
                    ldm4(bb, bBase + (uint32_t)(jp * (16 * BSTB) + ks * 32));
                    mma16816(acc[0][jp * 2 + 0], a0, bb);
                    mma16816(acc[0][jp * 2 + 1], a0, bb + 2);
                    mma16816(acc[1][jp * 2 + 0], a1, bb);
                    mma16816(acc[1][jp * 2 + 1], a1, bb + 2);
                }
            }
        }

        // running argmax + 2nd max over this 128-key tile
        #pragma unroll
        for (int j = 0; j < 8; j++) {
            int col0 = nt * 128 + wN * 64 + j * 8 + 2 * qk;
            #pragma unroll
            for (int mt = 0; mt < 2; mt++)
                #pragma unroll
                for (int rr = 0; rr < 2; rr++) {
                    int r = mt * 2 + rr;
                    float v0 = acc[mt][j][rr * 2 + 0];
                    float v1 = acc[mt][j][rr * 2 + 1];
                    if (v0 > bv[r]) { bv2[r] = bv[r]; bv[r] = v0; bi[r] = col0; }
                    else            { bv2[r] = fmaxf(bv2[r], v0); }
                    if (v1 > bv[r]) { bv2[r] = bv[r]; bv[r] = v1; bi[r] = col0 + 1; }
                    else            { bv2[r] = fmaxf(bv2[r], v1); }
                }
        }
    }
    __syncthreads();   // all compute done before reduce scratch reuses B area

    // ---- quad reduce ----
    #pragma unroll
    for (int off = 1; off <= 2; off <<= 1) {
        #pragma unroll
        for (int r = 0; r < 4; r++) {
            float ov  = __shfl_xor_sync(0xFFFFFFFFu, bv[r],  off);
            int   oi  = __shfl_xor_sync(0xFFFFFFFFu, bi[r],  off);
            float ov2 = __shfl_xor_sync(0xFFFFFFFFu, bv2[r], off);
            if (ov > bv[r]) { bv2[r] = fmaxf(bv[r], ov2); bv[r] = ov; bi[r] = oi; }
            else {
                if (ov == bv[r] && oi < bi[r]) bi[r] = oi;
                bv2[r] = fmaxf(bv2[r], ov);
            }
        }
    }

    // ---- cross-warp (wN) reduce ----
    float* rv  = (float*)(sm + RED_V);
    int*   ri  = (int*)  (sm + RED_I);
    float* rv2 = (float*)(sm + RED_V2);
    int*   rfi = (int*)  (sm + RED_FI);
    if (qk == 0) {
        #pragma unroll
        for (int r = 0; r < 4; r++) {
            int mt = r >> 1, rr = r & 1;
            int row = wM * 32 + mt * 16 + rr * 8 + qrow;
            rv [row * 2 + wN] = bv[r];
            ri [row * 2 + wN] = bi[r];
            rv2[row * 2 + wN] = bv2[r];
        }
    }
    __syncthreads();
    if (tid < 128) {
        float fv = rv[tid * 2], fv2 = rv2[tid * 2];
        int   fi = ri[tid * 2];
        float ov = rv[tid * 2 + 1], ov2 = rv2[tid * 2 + 1];
        int   oi = ri[tid * 2 + 1];
        if (ov > fv) { fv2 = fmaxf(fv, ov2); fv = ov; fi = oi; }
        else {
            if (ov == fv && oi < fi) fi = oi;
            fv2 = fmaxf(fv2, ov);
        }
        int b = bm0 + tid;
        g_idx[b] = fi;
        rfi[tid] = fi;
        if (fv - fv2 < THRESH) {
            int p = atomicAdd(&g_nflag, 1);
            g_flagged[p] = b;          // rescore votes + rewrites out row
        } else {
            atomicMax(&g_winner[fi], b);
        }
    }
    __syncthreads();

    // ---- fused gather: out_read[bm0+row] = vals[rfi[row]] ----
    {
        const float4* v4 = (const float4*)vals;
        float4* o4 = (float4*)(out_read + (size_t)bm0 * DD);
        #pragma unroll
        for (int i = tid; i < 128 * 64; i += 256) {
            int row = i >> 6, c4 = i & 63;
            stcs4(&o4[(size_t)row * 64 + c4], v4[(size_t)rfi[row] * 64 + c4]);
        }
    }
}

// ---------------------------------------------------------------------------
// Stage 2: exact fp32 rescore — 4 rows per block-iteration, register-blocked.
// Thread t handles keys t, 256+t, 512+t, 768+t (ascending). Inner loop over
// d4 hoists qv[4 rows] and kv[4 keys] into registers => FMA-bound.
// Per-(row,key) accumulation order: d4 ascending, x,y,z,w — identical to
// the R12 rescore => bit-identical scores and tie semantics.
// ---------------------------------------------------------------------------
#define RR 4
__global__ void __launch_bounds__(256)
rescore_kernel(const float* __restrict__ q, const float* __restrict__ vals,
               float* __restrict__ out_read, int S) {
    __shared__ float sq[RR * 256];
    __shared__ float rv[RR][8];
    __shared__ int   rix[RR][8];
    __shared__ int   sfi[RR];
    const int tid  = threadIdx.x;
    const int wid  = tid >> 5;
    const int lane = tid & 31;
    const int nf = g_nflag;

    for (int base = blockIdx.x * RR; base < nf; base += gridDim.x * RR) {
        int nr = min(RR, nf - base);
        for (int i = tid; i < nr * 256; i += 256) {
            int r = i >> 8, d = i & 255;
            sq[r * 256 + d] = q[(size_t)g_flagged[base + r] * 256 + d];
        }
        __syncthreads();

        // acc[key][row]
        float acc[4][RR];
        #pragma unroll
        for (int kq = 0; kq < 4; kq++)
            #pragma unroll
            for (int r = 0; r < RR; r++) acc[kq][r] = 0.0f;

        const float4* kr0 = (const float4*)(g_kn + (size_t)(0 * 256 + tid) * DD);
        const float4* kr1 = (const float4*)(g_kn + (size_t)(1 * 256 + tid) * DD);
        const float4* kr2 = (const float4*)(g_kn + (size_t)(2 * 256 + tid) * DD);
        const float4* kr3 = (const float4*)(g_kn + (size_t)(3 * 256 + tid) * DD);

        #pragma unroll 4
        for (int d4 = 0; d4 < 64; d4++) {
            float4 kv0 = kr0[d4], kv1 = kr1[d4], kv2 = kr2[d4], kv3 = kr3[d4];
            #pragma unroll
            for (int r = 0; r < RR; r++) {
                const float4 qv = *(const float4*)&sq[r * 256 + d4 * 4];
                acc[0][r] = fmaf(qv.x, kv0.x, acc[0][r]);
                acc[0][r] = fmaf(qv.y, kv0.y, acc[0][r]);
                acc[0][r] = fmaf(qv.z, kv0.z, acc[0][r]);
                acc[0][r] = fmaf(qv.w, kv0.w, acc[0][r]);
                acc[1][r] = fmaf(qv.x, kv1.x, acc[1][r]);
                acc[1][r] = fmaf(qv.y, kv1.y, acc[1][r]);
                acc[1][r] = fmaf(qv.z, kv1.z, acc[1][r]);
                acc[1][r] = fmaf(qv.w, kv1.w, acc[1][r]);
                acc[2][r] = fmaf(qv.x, kv2.x, acc[2][r]);
                acc[2][r] = fmaf(qv.y, kv2.y, acc[2][r]);
                acc[2][r] = fmaf(qv.z, kv2.z, acc[2][r]);
                acc[2][r] = fmaf(qv.w, kv2.w, acc[2][r]);
                acc[3][r] = fmaf(qv.x, kv3.x, acc[3][r]);
                acc[3][r] = fmaf(qv.y, kv3.y, acc[3][r]);
                acc[3][r] = fmaf(qv.z, kv3.z, acc[3][r]);
                acc[3][r] = fmaf(qv.w, kv3.w, acc[3][r]);
            }
        }

        // per-thread best over its 4 keys (ascending => strict > keeps lowest)
        float bvl[RR]; int bil[RR];
        #pragma unroll
        for (int r = 0; r < RR; r++) { bvl[r] = -FLT_MAX; bil[r] = 0; }
        #pragma unroll
        for (int kq = 0; kq < 4; kq++) {
            int s = kq * 256 + tid;
            #pragma unroll
            for (int r = 0; r < RR; r++)
                if (acc[kq][r] > bvl[r]) { bvl[r] = acc[kq][r]; bil[r] = s; }
        }

        // warp reduce (tie -> lower idx)
        #pragma unroll
        for (int off = 16; off; off >>= 1) {
            #pragma unroll
            for (int r = 0; r < RR; r++) {
                float ov = __shfl_xor_sync(0xFFFFFFFFu, bvl[r], off);
                int   oi = __shfl_xor_sync(0xFFFFFFFFu, bil[r], off);
                if (ov > bvl[r] || (ov == bvl[r] && oi < bil[r])) { bvl[r] = ov; bil[r] = oi; }
            }
        }
        if (lane == 0) {
            #pragma unroll
            for (int r = 0; r < RR; r++) { rv[r][wid] = bvl[r]; rix[r][wid] = bil[r]; }
        }
        __syncthreads();
        if (tid < nr) {
            float fv = -FLT_MAX; int fi = S;
            #pragma unroll
            for (int w = 0; w < 8; w++) {
                float v = rv[tid][w]; int i = rix[tid][w];
                if (v > fv || (v == fv && i < fi)) { fv = v; fi = i; }
            }
            int b = g_flagged[base + tid];
            g_idx[b] = fi;
            sfi[tid] = fi;
            atomicMax(&g_winner[fi], b);
        }
        __syncthreads();
        // rewrite out_read rows for flagged queries
        for (int i = tid; i < nr * 64; i += 256) {
            int r = i >> 6, c4 = i & 63;
            int b = g_flagged[base + r];
            stcs4(&((float4*)(out_read + (size_t)b * 256))[c4],
                  ((const float4*)(vals + (size_t)sfi[r] * 256))[c4]);
        }
        __syncthreads();
    }
}

// ---------------------------------------------------------------------------
// Gated scatter update
// ---------------------------------------------------------------------------
__global__ void update_kernel(const float* __restrict__ q,
                              const float* __restrict__ tgt,
                              const float* __restrict__ sur,
                              const float* __restrict__ keys,
                              const float* __restrict__ vals,
                              float* __restrict__ outK,
                              float* __restrict__ outV, int D) {
    int s = blockIdx.x;
    int d = threadIdx.x;
    int b = g_winner[s];
    float k = keys[(size_t)s * D + d];
    float v = vals[(size_t)s * D + d];
    if (b >= 0) {
        float g  = (1.0f / (1.0f + expf(-4.0f * sur[b]))) * LR;
        float om = 1.0f - g;
        outK[(size_t)s * D + d] = om * k + g * q[(size_t)b * D + d];
        outV[(size_t)s * D + d] = om * v + g * tgt[(size_t)b * D + d];
    } else {
        outK[(size_t)s * D + d] = k;
        outV[(size_t)s * D + d] = v;
    }
}

// ---------------------------------------------------------------------------
extern "C" void kernel_launch(void* const* d_in, const int* in_sizes, int n_in,
                              void* d_out, int out_size) {
    const float* query    = (const float*)d_in[0];
    const float* target   = (const float*)d_in[1];
    const float* surprise = (const float*)d_in[2];
    const float* keys     = (const float*)d_in[3];
    const float* vals     = (const float*)d_in[4];

    const int B = in_sizes[2];
    const int D = in_sizes[0] / B;     // 256
    const int S = in_sizes[3] / D;     // 1024

    float* out      = (float*)d_out;
    float* out_read = out;
    float* out_keys = out + (size_t)B * D;
    float* out_vals = out + (size_t)(B + S) * D;

    knorm_kernel<<<S, 256>>>(keys, S, D);

    cudaFuncSetAttribute(score_argmax_kernel,
                         cudaFuncAttributeMaxDynamicSharedMemorySize, SM_TOTAL);
    score_argmax_kernel<<<B / 128, 256, SM_TOTAL>>>(query, vals, out_read, B, S);

    rescore_kernel<<<2048, 256>>>(query, vals, out_read, S);

    update_kernel<<<S, 256>>>(query, target, surprise, keys, vals,
                              out_keys, out_vals, D);
}

// round 15
// speedup vs baseline: 2.9630x; 1.5500x over previous
#include <cuda_runtime.h>
#include <cuda_fp16.h>
#include <math.h>
#include <float.h>
#include <stdint.h>

#define EPS 1e-8f
#define LR  0.1f
#define THRESH 5e-3f

#define MAXB 131072
#define MAXS 1024
#define DD   256

// Global scratch
__device__ float  g_knT[DD * MAXS];           // transposed normalized keys [d][s]
__device__ __half g_kh[(size_t)MAXS * DD];    // normalized keys fp16 (GEMM)
__device__ int    g_idx[MAXB];
__device__ int    g_winner[MAXS];
__device__ int    g_flagged[MAXB];
__device__ int    g_nflag;

// ---------------------------------------------------------------------------
__device__ __forceinline__ uint32_t smem_u32(const void* p) {
    uint32_t a;
    asm("{ .reg .u64 t; cvta.to.shared.u64 t, %1; cvt.u32.u64 %0, t; }" : "=r"(a) : "l"(p));
    return a;
}
__device__ __forceinline__ void cpasync16(uint32_t saddr, const void* gaddr) {
    asm volatile("cp.async.cg.shared.global [%0], [%1], 16;" :: "r"(saddr), "l"(gaddr));
}
#define CP_COMMIT()  asm volatile("cp.async.commit_group;" ::: "memory")
#define CP_WAIT(n)   asm volatile("cp.async.wait_group %0;" :: "n"(n) : "memory")

__device__ __forceinline__ void ldm4(uint32_t* d, uint32_t addr) {
    asm volatile("ldmatrix.sync.aligned.m8n8.x4.shared.b16 {%0,%1,%2,%3}, [%4];"
        : "=r"(d[0]), "=r"(d[1]), "=r"(d[2]), "=r"(d[3]) : "r"(addr));
}
__device__ __forceinline__ void mma16816(float* c, const uint32_t* a, const uint32_t* b) {
    asm volatile(
        "mma.sync.aligned.m16n8k16.row.col.f32.f16.f16.f32 "
        "{%0,%1,%2,%3}, {%4,%5,%6,%7}, {%8,%9}, {%0,%1,%2,%3};"
        : "+f"(c[0]), "+f"(c[1]), "+f"(c[2]), "+f"(c[3])
        : "r"(a[0]), "r"(a[1]), "r"(a[2]), "r"(a[3]), "r"(b[0]), "r"(b[1]));
}
__device__ __forceinline__ float4 ldcs4(const float4* p) {
    float4 v;
    asm volatile("ld.global.cs.v4.f32 {%0,%1,%2,%3}, [%4];"
        : "=f"(v.x), "=f"(v.y), "=f"(v.z), "=f"(v.w) : "l"(p));
    return v;
}
__device__ __forceinline__ void stcs4(float4* p, float4 v) {
    asm volatile("st.global.cs.v4.f32 [%0], {%1,%2,%3,%4};"
        :: "l"(p), "f"(v.x), "f"(v.y), "f"(v.z), "f"(v.w) : "memory");
}

// ---------------------------------------------------------------------------
// Prep: normalize keys -> transposed fp32 + fp16; init winner=-1, nflag=0
// ---------------------------------------------------------------------------
__global__ void knorm_kernel(const float* __restrict__ keys, int S, int D) {
    int s = blockIdx.x;
    int t = threadIdx.x;
    __shared__ float red[8];
    __shared__ float s_nrm;
    float v = keys[(size_t)s * D + t];
    float sq = v * v;
    #pragma unroll
    for (int o = 16; o; o >>= 1) sq += __shfl_xor_sync(0xFFFFFFFFu, sq, o);
    if ((t & 31) == 0) red[t >> 5] = sq;
    __syncthreads();
    if (t == 0) {
        float tot = 0.0f;
        #pragma unroll
        for (int i = 0; i < 8; i++) tot += red[i];
        s_nrm = fmaxf(sqrtf(tot), EPS);
        g_winner[s] = -1;
        if (s == 0) g_nflag = 0;
    }
    __syncthreads();
    float kn = v / s_nrm;
    g_knT[t * S + s] = kn;                 // transposed [d][s]
    g_kh[(size_t)s * D + t] = __float2half_rn(kn);
}

// ---------------------------------------------------------------------------
// Stage 1: fp16 m16n8k16 (f32 acc) GEMM + argmax + gap filter + fused gather.
// CTA: 128 query rows, 256 threads, 8 warps = 4 wM x 2 wN, 2 CTAs/SM.
// (identical to R11 — measured ~93% of rt8 HMMA floor)
// ---------------------------------------------------------------------------
#define ASTB 528                      // A row stride bytes
#define BSTB 144                      // B row stride bytes
#define SM_A   0
#define SM_B   (128 * ASTB)           // 67584
#define BBUF   (128 * BSTB)           // 18432
#define SM_TOTAL (SM_B + 2 * BBUF)    // 104448
#define RED_V  (SM_B)
#define RED_I  (SM_B + 128*2*4)
#define RED_V2 (SM_B + 128*2*4*2)
#define RED_FI (SM_B + 128*2*4*3)

__global__ void __launch_bounds__(256, 2)
score_argmax_kernel(const float* __restrict__ q,
                    const float* __restrict__ vals,
                    float* __restrict__ out_read, int B, int S) {
    extern __shared__ char sm[];
    const uint32_t smb = smem_u32(sm);
    const int tid  = threadIdx.x;
    const int wid  = tid >> 5;
    const int lane = tid & 31;
    const int wM   = wid >> 1;        // 0..3
    const int wN   = wid & 1;         // 0..1
    const int qrow = lane >> 2;       // 0..7
    const int qk   = lane & 3;        // 0..3
    const int bm0  = blockIdx.x * 128;

    const int n_chunks = (S / 128) * 4;   // 32
    auto issueB = [&](int c) {
        int nt = c >> 2, kc = c & 3, buf = c & 1;
        #pragma unroll
        for (int i = 0; i < 4; i++) {
            int s2  = tid + i * 256;
            int row = s2 >> 3, seg = s2 & 7;
            const __half* g = g_kh + (size_t)(nt * 128 + row) * DD + kc * 64 + seg * 8;
            cpasync16(smb + SM_B + buf * BBUF + (uint32_t)(row * BSTB + seg * 16), g);
        }
        CP_COMMIT();
    };

    issueB(0);

    // ---- A: load q fp32 (evict-first), convert fp16, store padded ----
    {
        const float* qb = q + (size_t)bm0 * DD;
        #pragma unroll
        for (int i = tid; i < 128 * 64; i += 256) {
            int r  = i >> 6;
            int c4 = (i & 63) * 4;
            float4 v = ldcs4((const float4*)(qb + (size_t)r * DD + c4));
            __half2 h0 = __floats2half2_rn(v.x, v.y);
            __half2 h1 = __floats2half2_rn(v.z, v.w);
            uint2 pk = { *(uint32_t*)&h0, *(uint32_t*)&h1 };
            *(uint2*)(sm + SM_A + r * ASTB + c4 * 2) = pk;
        }
    }

    const uint32_t aBase = smb + SM_A +
        (uint32_t)((wM * 32 + ((lane >> 3) & 1) * 8 + (lane & 7)) * ASTB + (lane >> 4) * 16);
    const uint32_t bBase0 = smb + SM_B +
        (uint32_t)((wN * 64 + ((lane >> 4) & 1) * 8 + (lane & 7)) * BSTB + ((lane >> 3) & 1) * 16);

    float bv[4], bv2[4];
    int   bi[4];
    #pragma unroll
    for (int r = 0; r < 4; r++) { bv[r] = -FLT_MAX; bv2[r] = -FLT_MAX; bi[r] = 0; }

    for (int nt = 0; nt < S / 128; nt++) {
        float acc[2][8][4];
        #pragma unroll
        for (int mt = 0; mt < 2; mt++)
            #pragma unroll
            for (int j = 0; j < 8; j++)
                #pragma unroll
                for (int e = 0; e < 4; e++) acc[mt][j][e] = 0.0f;

        #pragma unroll
        for (int kc = 0; kc < 4; kc++) {
            const int c = nt * 4 + kc;
            const int buf = c & 1;
            CP_WAIT(0);
            __syncthreads();               // chunk-c data visible AND compute(c-1) done
            if (c + 1 < n_chunks) issueB(c + 1);

            const uint32_t bBase = bBase0 + (uint32_t)buf * BBUF;

            #pragma unroll
            for (int ks = 0; ks < 4; ks++) {
                uint32_t a0[4], a1[4];
                ldm4(a0, aBase + (uint32_t)(kc * 128 + ks * 32));
                ldm4(a1, aBase + (uint32_t)(16 * ASTB + kc * 128 + ks * 32));
                #pragma unroll
                for (int jp = 0; jp < 4; jp++) {
                    uint32_t bb[4];
                    ldm4(bb, bBase + (uint32_t)(jp * (16 * BSTB) + ks * 32));
                    mma16816(acc[0][jp * 2 + 0], a0, bb);
                    mma16816(acc[0][jp * 2 + 1], a0, bb + 2);
                    mma16816(acc[1][jp * 2 + 0], a1, bb);
                    mma16816(acc[1][jp * 2 + 1], a1, bb + 2);
                }
            }
        }

        // running argmax + 2nd max over this 128-key tile
        #pragma unroll
        for (int j = 0; j < 8; j++) {
            int col0 = nt * 128 + wN * 64 + j * 8 + 2 * qk;
            #pragma unroll
            for (int mt = 0; mt < 2; mt++)
                #pragma unroll
                for (int rr = 0; rr < 2; rr++) {
                    int r = mt * 2 + rr;
                    float v0 = acc[mt][j][rr * 2 + 0];
                    float v1 = acc[mt][j][rr * 2 + 1];
                    if (v0 > bv[r]) { bv2[r] = bv[r]; bv[r] = v0; bi[r] = col0; }
                    else            { bv2[r] = fmaxf(bv2[r], v0); }
                    if (v1 > bv[r]) { bv2[r] = bv[r]; bv[r] = v1; bi[r] = col0 + 1; }
                    else            { bv2[r] = fmaxf(bv2[r], v1); }
                }
        }
    }
    __syncthreads();   // all compute done before reduce scratch reuses B area

    // ---- quad reduce ----
    #pragma unroll
    for (int off = 1; off <= 2; off <<= 1) {
        #pragma unroll
        for (int r = 0; r < 4; r++) {
            float ov  = __shfl_xor_sync(0xFFFFFFFFu, bv[r],  off);
            int   oi  = __shfl_xor_sync(0xFFFFFFFFu, bi[r],  off);
            float ov2 = __shfl_xor_sync(0xFFFFFFFFu, bv2[r], off);
            if (ov > bv[r]) { bv2[r] = fmaxf(bv[r], ov2); bv[r] = ov; bi[r] = oi; }
            else {
                if (ov == bv[r] && oi < bi[r]) bi[r] = oi;
                bv2[r] = fmaxf(bv2[r], ov);
            }
        }
    }

    // ---- cross-warp (wN) reduce ----
    float* rv  = (float*)(sm + RED_V);
    int*   ri  = (int*)  (sm + RED_I);
    float* rv2 = (float*)(sm + RED_V2);
    int*   rfi = (int*)  (sm + RED_FI);
    if (qk == 0) {
        #pragma unroll
        for (int r = 0; r < 4; r++) {
            int mt = r >> 1, rr = r & 1;
            int row = wM * 32 + mt * 16 + rr * 8 + qrow;
            rv [row * 2 + wN] = bv[r];
            ri [row * 2 + wN] = bi[r];
            rv2[row * 2 + wN] = bv2[r];
        }
    }
    __syncthreads();
    if (tid < 128) {
        float fv = rv[tid * 2], fv2 = rv2[tid * 2];
        int   fi = ri[tid * 2];
        float ov = rv[tid * 2 + 1], ov2 = rv2[tid * 2 + 1];
        int   oi = ri[tid * 2 + 1];
        if (ov > fv) { fv2 = fmaxf(fv, ov2); fv = ov; fi = oi; }
        else {
            if (ov == fv && oi < fi) fi = oi;
            fv2 = fmaxf(fv2, ov);
        }
        int b = bm0 + tid;
        g_idx[b] = fi;
        rfi[tid] = fi;
        if (fv - fv2 < THRESH) {
            int p = atomicAdd(&g_nflag, 1);
            g_flagged[p] = b;          // rescore votes + rewrites out row
        } else {
            atomicMax(&g_winner[fi], b);
        }
    }
    __syncthreads();

    // ---- fused gather: out_read[bm0+row] = vals[rfi[row]] ----
    {
        const float4* v4 = (const float4*)vals;
        float4* o4 = (float4*)(out_read + (size_t)bm0 * DD);
        #pragma unroll
        for (int i = tid; i < 128 * 64; i += 256) {
            int row = i >> 6, c4 = i & 63;
            stcs4(&o4[(size_t)row * 64 + c4], v4[(size_t)rfi[row] * 64 + c4]);
        }
    }
}

// ---------------------------------------------------------------------------
// Stage 2: exact fp32 rescore — transposed keys, coalesced.
// 8 flagged rows per block iteration. Thread t owns keys 4t..4t+3 (ascending);
// per d-step: one coalesced LDG.128 of 4 consecutive keys + broadcast LDS.
// Accumulation strictly d-ascending per (row,key) — bit-identical scores and
// tie semantics to all prior rescores.
// ---------------------------------------------------------------------------
#define RR 8
__global__ void __launch_bounds__(256)
rescore_kernel(const float* __restrict__ q, const float* __restrict__ vals,
               float* __restrict__ out_read, int S) {
    __shared__ float sq[RR * 256];
    __shared__ float rv[RR][8];
    __shared__ int   rix[RR][8];
    __shared__ int   sfi[RR];
    const int tid  = threadIdx.x;
    const int wid  = tid >> 5;
    const int lane = tid & 31;
    const int nf = g_nflag;

    for (int base = blockIdx.x * RR; base < nf; base += gridDim.x * RR) {
        int nr = min(RR, nf - base);
        for (int i = tid; i < nr * 256; i += 256) {
            int r = i >> 8, d = i & 255;
            sq[r * 256 + d] = q[(size_t)g_flagged[base + r] * 256 + d];
        }
        __syncthreads();

        // acc[key 0..3][row]: keys 4*tid + k
        float acc[4][RR];
        #pragma unroll
        for (int k = 0; k < 4; k++)
            #pragma unroll
            for (int r = 0; r < RR; r++) acc[k][r] = 0.0f;

        #pragma unroll 4
        for (int d = 0; d < 256; d++) {
            float4 kv = ((const float4*)(g_knT + d * S))[tid];  // keys 4t..4t+3
            #pragma unroll
            for (int r = 0; r < RR; r++) {
                float qd = sq[r * 256 + d];      // broadcast
                acc[0][r] = fmaf(qd, kv.x, acc[0][r]);
                acc[1][r] = fmaf(qd, kv.y, acc[1][r]);
                acc[2][r] = fmaf(qd, kv.z, acc[2][r]);
                acc[3][r] = fmaf(qd, kv.w, acc[3][r]);
            }
        }

        // per-thread best over its 4 keys (ascending => strict > keeps lowest)
        float bvl[RR]; int bil[RR];
        #pragma unroll
        for (int r = 0; r < RR; r++) { bvl[r] = -FLT_MAX; bil[r] = 0; }
        #pragma unroll
        for (int k = 0; k < 4; k++) {
            int s = 4 * tid + k;
            #pragma unroll
            for (int r = 0; r < RR; r++)
                if (acc[k][r] > bvl[r]) { bvl[r] = acc[k][r]; bil[r] = s; }
        }

        // warp reduce (tie -> lower idx)
        #pragma unroll
        for (int off = 16; off; off >>= 1) {
            #pragma unroll
            for (int r = 0; r < RR; r++) {
                float ov = __shfl_xor_sync(0xFFFFFFFFu, bvl[r], off);
                int   oi = __shfl_xor_sync(0xFFFFFFFFu, bil[r], off);
                if (ov > bvl[r] || (ov == bvl[r] && oi < bil[r])) { bvl[r] = ov; bil[r] = oi; }
            }
        }
        if (lane == 0) {
            #pragma unroll
            for (int r = 0; r < RR; r++) { rv[r][wid] = bvl[r]; rix[r][wid] = bil[r]; }
        }
        __syncthreads();
        if (tid < nr) {
            float fv = -FLT_MAX; int fi = S;
            #pragma unroll
            for (int w = 0; w < 8; w++) {
                float v = rv[tid][w]; int i = rix[tid][w];
                if (v > fv || (v == fv && i < fi)) { fv = v; fi = i; }
            }
            int b = g_flagged[base + tid];
            g_idx[b] = fi;
            sfi[tid] = fi;
            atomicMax(&g_winner[fi], b);
        }
        __syncthreads();
        // rewrite out_read rows for flagged queries
        for (int i = tid; i < nr * 64; i += 256) {
            int r = i >> 6, c4 = i & 63;
            int b = g_flagged[base + r];
            stcs4(&((float4*)(out_read + (size_t)b * 256))[c4],
                  ((const float4*)(vals + (size_t)sfi[r] * 256))[c4]);
        }
        __syncthreads();
    }
}

// ---------------------------------------------------------------------------
// Gated scatter update
// ---------------------------------------------------------------------------
__global__ void update_kernel(const float* __restrict__ q,
                              const float* __restrict__ tgt,
                              const float* __restrict__ sur,
                              const float* __restrict__ keys,
                              const float* __restrict__ vals,
                              float* __restrict__ outK,
                              float* __restrict__ outV, int D) {
    int s = blockIdx.x;
    int d = threadIdx.x;
    int b = g_winner[s];
    float k = keys[(size_t)s * D + d];
    float v = vals[(size_t)s * D + d];
    if (b >= 0) {
        float g  = (1.0f / (1.0f + expf(-4.0f * sur[b]))) * LR;
        float om = 1.0f - g;
        outK[(size_t)s * D + d] = om * k + g * q[(size_t)b * D + d];
        outV[(size_t)s * D + d] = om * v + g * tgt[(size_t)b * D + d];
    } else {
        outK[(size_t)s * D + d] = k;
        outV[(size_t)s * D + d] = v;
    }
}

// ---------------------------------------------------------------------------
extern "C" void kernel_launch(void* const* d_in, const int* in_sizes, int n_in,
                              void* d_out, int out_size) {
    const float* query    = (const float*)d_in[0];
    const float* target   = (const float*)d_in[1];
    const float* surprise = (const float*)d_in[2];
    const float* keys     = (const float*)d_in[3];
    const float* vals     = (const float*)d_in[4];

    const int B = in_sizes[2];
    const int D = in_sizes[0] / B;     // 256
    const int S = in_sizes[3] / D;     // 1024

    float* out      = (float*)d_out;
    float* out_read = out;
    float* out_keys = out + (size_t)B * D;
    float* out_vals = out + (size_t)(B + S) * D;

    knorm_kernel<<<S, 256>>>(keys, S, D);

    cudaFuncSetAttribute(score_argmax_kernel,
                         cudaFuncAttributeMaxDynamicSharedMemorySize, SM_TOTAL);
    score_argmax_kernel<<<B / 128, 256, SM_TOTAL>>>(query, vals, out_read, B, S);

    rescore_kernel<<<1024, 256>>>(query, vals, out_read, S);

    update_kernel<<<S, 256>>>(query, target, surprise, keys, vals,
                              out_keys, out_vals, D);
}